// round 15
// baseline (speedup 1.0000x reference)
#include <cuda_runtime.h>
#include <cstdint>

// ============================================================================
// Stacked LSTM (H1=51, H2=1), B=2048, T=1024 (+F=64 autoregressive steps).
//
// Round 15: unit-split warp teams.
//   - Team = 2 warps serving V=8 batch elements. Warp0 owns h1-units 0..25,
//     warp1 units 26..50(+pad). Each lane: ONE unit x 8 elements.
//   - Weight crossbar traffic per element drops 3.2x (each warp reads only
//     its 26 weight columns; zero wasted pad FMAs).
//   - h1 exchanged via double-buffered smem + one __syncthreads per step.
//   - LSTM2: 8 elems x 4 gates = exactly 32 lanes, one full 51-dot per lane
//     from smem (broadcast), 4 shfls gather gates; computed redundantly in
//     both warps (bit-identical) so future-phase feedback needs no exchange.
//     Deferred one step to overlap with the k-loop.
//   - FFMA2 packed gate pairs, tanh.approx activations (as rounds 13/14).
// ============================================================================

#define FULLMASK 0xffffffffu
#define H1 51
#define KP 52

typedef unsigned long long ull;

#define FMA2(d, a, b, c) \
    asm("fma.rn.f32x2 %0, %1, %2, %3;" : "=l"(d) : "l"(a), "l"(b), "l"(c))

__device__ __forceinline__ ull pack2(float lo, float hi) {
    ull r; asm("mov.b64 %0, {%1, %2};" : "=l"(r) : "f"(lo), "f"(hi)); return r;
}
__device__ __forceinline__ ull dup2(float x) {
    ull r; asm("mov.b64 %0, {%1, %1};" : "=l"(r) : "f"(x)); return r;
}
__device__ __forceinline__ float2 unpack2(ull v) {
    float2 r; asm("mov.b64 {%0, %1}, %2;" : "=f"(r.x), "=f"(r.y) : "l"(v)); return r;
}

__device__ __forceinline__ float ftanh(float x) {
    float r; asm("tanh.approx.f32 %0, %1;" : "=f"(r) : "f"(x)); return r;
}
__device__ __forceinline__ float fsig(float x) {
    return fmaf(0.5f, ftanh(0.5f * x), 0.5f);
}

__global__ void __launch_bounds__(64, 1) lstm_seq_kernel(
    const float* __restrict__ input,   // [B, T]
    const float* __restrict__ Wih1,    // [204, 1]
    const float* __restrict__ Whh1,    // [204, 51]
    const float* __restrict__ bih1,    // [204]
    const float* __restrict__ bhh1,    // [204]
    const float* __restrict__ Wih2,    // [4, 51]
    const float* __restrict__ Whh2,    // [4, 1]
    const float* __restrict__ bih2,    // [4]
    const float* __restrict__ bhh2,    // [4]
    float* __restrict__ out,           // [B, T+F]
    int T, int TF)
{
    // W1s[k][u]: float4 gate weights (i,f,g,o), row 51 / col 51 zero pad.
    __shared__ float4 W1s[KP * KP];    // 43264 B
    __shared__ float4 W2s[4 * 13];     //   832 B  Wih2[g][k] chunked
    __shared__ float4 Hs[2][8][13];    //  3328 B  [buf][elem][chunk] h1
                                       // total 47424 B < 48KB static limit

    const int tid = threadIdx.x;

    // ---- init shared ----
    for (int idx = tid; idx < KP * KP; idx += 64) {
        int k = idx / KP, u = idx % KP;
        float4 w = make_float4(0.f, 0.f, 0.f, 0.f);
        if (k < H1 && u < H1) {
            w.x = Whh1[(0 * H1 + u) * H1 + k];
            w.y = Whh1[(1 * H1 + u) * H1 + k];
            w.z = Whh1[(2 * H1 + u) * H1 + k];
            w.w = Whh1[(3 * H1 + u) * H1 + k];
        }
        W1s[idx] = w;
    }
    for (int idx = tid; idx < 4 * 13; idx += 64) {
        int g = idx / 13, c = idx % 13;
        float4 w = make_float4(0.f, 0.f, 0.f, 0.f);
        float* wf = (float*)&w;
        for (int j = 0; j < 4; j++) {
            int k = c * 4 + j;
            if (k < H1) wf[j] = Wih2[g * H1 + k];
        }
        W2s[idx] = w;
    }
    for (int idx = tid; idx < 2 * 8 * 13; idx += 64)
        ((float4*)Hs)[idx] = make_float4(0.f, 0.f, 0.f, 0.f);
    __syncthreads();

    const ulonglong2* __restrict__ W1u = reinterpret_cast<const ulonglong2*>(W1s);

    const int lane = tid & 31;
    const int wid  = tid >> 5;
    const int uraw = wid * 26 + lane;       // warp0: 0..31, warp1: 26..57
    const bool real = uraw < H1;            // owns a real unit
    const int  u    = real ? uraw : H1;     // pad column 51 otherwise

    // ---- per-unit input weights / bias (zero for pad lanes) ----
    float Wi[4], bi[4];
#pragma unroll
    for (int g = 0; g < 4; g++) {
        int ui = real ? uraw : 0;
        float wv = Wih1[g * H1 + ui];
        float bv = bih1[g * H1 + ui] + bhh1[g * H1 + ui];
        Wi[g] = real ? wv : 0.f;
        bi[g] = real ? bv : 0.f;
    }
    const ull Wip0 = pack2(Wi[0], Wi[1]), Wip1 = pack2(Wi[2], Wi[3]);
    const ull bp0  = pack2(bi[0], bi[1]), bp1  = pack2(bi[2], bi[3]);

    // LSTM2 lane mapping: 8 elems x 4 gates = 32 lanes exactly
    const int e2 = lane >> 2;
    const int g2 = lane & 3;
    const float W2h_l = Whh2[g2];
    const float b2_l  = bih2[g2] + bhh2[g2];

    // ---- state ----
    float c1[8];
#pragma unroll
    for (int e = 0; e < 8; e++) c1[e] = 0.f;
    float h2v = 0.f, c2v = 0.f;     // LSTM2 state (identical in both warps)

    const int bbase = blockIdx.x * 8;
    const float* inp[8];
#pragma unroll
    for (int e = 0; e < 8; e++) inp[e] = input + (size_t)(bbase + e) * T;
    float* outw = (wid == 0 && g2 == 0)
                ? out + (size_t)(bbase + e2) * TF : nullptr;

#pragma unroll 1
    for (int t = 0; t <= TF; t++) {
        const int pb = (t & 1) ^ 1;        // buffer holding h1(t-1)

        // ---- deferred LSTM2 for step t-1 (reads h1(t-1); overlaps k-loop
        //      in the main phase; supplies x=h2 in the future phase) ----
        if (t > 0) {
            float acc0 = 0.f, acc1 = 0.f;
#pragma unroll
            for (int c = 0; c < 13; c++) {
                float4 hv = Hs[pb][e2][c];
                float4 wv = W2s[g2 * 13 + c];
                acc0 = fmaf(hv.x, wv.x, fmaf(hv.y, wv.y, acc0));
                acc1 = fmaf(hv.z, wv.z, fmaf(hv.w, wv.w, acc1));
            }
            float pre = acc0 + acc1 + W2h_l * h2v + b2_l;
            const int base = lane & ~3;
            float pi = __shfl_sync(FULLMASK, pre, base + 0);
            float pf = __shfl_sync(FULLMASK, pre, base + 1);
            float pg = __shfl_sync(FULLMASK, pre, base + 2);
            float po = __shfl_sync(FULLMASK, pre, base + 3);
            float i2 = fsig(pi), f2 = fsig(pf), gg = ftanh(pg), o2 = fsig(po);
            c2v = f2 * c2v + i2 * gg;
            h2v = o2 * ftanh(c2v);
            if (outw) outw[t - 1] = h2v;
        }
        if (t == TF) break;

        // ---- LSTM1 input: data in main phase, own h2 in future phase ----
        float x[8];
        if (t < T) {
#pragma unroll
            for (int e = 0; e < 8; e++) x[e] = __ldg(inp[e] + t);
        } else {
#pragma unroll
            for (int e = 0; e < 8; e++)
                x[e] = __shfl_sync(FULLMASK, h2v, e << 2);
        }

        // ---- gate accumulators: pair0=(i,f), pair1=(g,o) per element ----
        ull a0[8], a1[8];
#pragma unroll
        for (int e = 0; e < 8; e++) {
            ull d = dup2(x[e]);
            FMA2(a0[e], d, Wip0, bp0);
            FMA2(a1[e], d, Wip1, bp1);
        }

        // ---- recurrent dot: 13 chunks x 4 k; h broadcast, own W column ----
#pragma unroll
        for (int kc = 0; kc < 13; kc++) {
            float4 hv[8];
#pragma unroll
            for (int e = 0; e < 8; e++) hv[e] = Hs[pb][e][kc];
#pragma unroll
            for (int j = 0; j < 4; j++) {
                const int k = kc * 4 + j;
                const ulonglong2 wv = W1u[k * KP + u];
#pragma unroll
                for (int e = 0; e < 8; e++) {
                    float hk = (j == 0) ? hv[e].x : (j == 1) ? hv[e].y
                             : (j == 2) ? hv[e].z : hv[e].w;
                    ull d = dup2(hk);
                    FMA2(a0[e], d, wv.x, a0[e]);
                    FMA2(a1[e], d, wv.y, a1[e]);
                }
            }
        }

        // ---- activations + cell update + publish h(t) ----
        const int cb = t & 1;
#pragma unroll
        for (int e = 0; e < 8; e++) {
            float2 v0 = unpack2(a0[e]), v1 = unpack2(a1[e]);
            float i = fsig(v0.x), f = fsig(v0.y);
            float g = ftanh(v1.x), o = fsig(v1.y);
            c1[e] = f * c1[e] + i * g;
            float h = o * ftanh(c1[e]);
            if (real) ((float*)&Hs[cb][e][0])[uraw] = h;
        }
        __syncthreads();   // h(t) visible to both warps before iter t+1
    }
}

extern "C" void kernel_launch(void* const* d_in, const int* in_sizes, int n_in,
                              void* d_out, int out_size) {
    const float* input = (const float*)d_in[0];
    const float* Wih1  = (const float*)d_in[1];
    const float* Whh1  = (const float*)d_in[2];
    const float* bih1  = (const float*)d_in[3];
    const float* bhh1  = (const float*)d_in[4];
    const float* Wih2  = (const float*)d_in[5];
    const float* Whh2  = (const float*)d_in[6];
    const float* bih2  = (const float*)d_in[7];
    const float* bhh2  = (const float*)d_in[8];
    float* out = (float*)d_out;

    const int B  = 2048;
    const int T  = in_sizes[0] / B;     // 1024
    const int TF = out_size / B;        // 1088

    // 1 team (2 warps) per block, 8 batch elements per team -> 256 blocks
    lstm_seq_kernel<<<B / 8, 64>>>(input, Wih1, Whh1, bih1, bhh1,
                                   Wih2, Whh2, bih2, bhh2,
                                   out, T, TF);
}